// round 11
// baseline (speedup 1.0000x reference)
#include <cuda_runtime.h>
#include <cuda_fp16.h>
#include <stdint.h>

#define DIM  768
#define DIM2 1536
#define DIM3 2304
#define MAX_S 2048
#define MAX_E 32768
#define MAX_N 100000
#define MAX_R 1000

// ---------------- fp32 scratch ----------------
__device__ float g_sub [MAX_S * DIM];
__device__ float g_gh  [MAX_S * DIM3];
__device__ float g_gi0 [MAX_S * DIM3];
__device__ float g_ghR [MAX_R * DIM3];
__device__ float g_obj [MAX_E * DIM];
__device__ float g_gi_enc[DIM3];
__device__ int   g_best[MAX_N];
__device__ int   g_seedpos[MAX_N];

// ---- fp16 A-operand scratch: [rows][1536], hi in [0,768), lo in [768,1536) ----
__device__ __half g_smasks[MAX_S * DIM2];
__device__ __half g_subs  [MAX_S * DIM2];
__device__ __half g_r0s   [MAX_S * DIM2];
__device__ __half g_rjs   [(size_t)MAX_E * DIM2];
__device__ __half g_rels  [MAX_R * DIM2];
// ---- fp16 W-operand scratch (hi only): [rows][768] ----
__device__ __half g_Wsubs [DIM  * DIM];
__device__ __half g_Wobjs [DIM  * DIM];
__device__ __half g_Wihs  [DIM3 * DIM];
__device__ __half g_Whhs  [DIM3 * DIM];

// ---------------- helpers ----------------
__device__ __forceinline__ uint32_t smem_u32(const void* p) {
    uint32_t a;
    asm("{ .reg .u64 t; cvta.to.shared.u64 t, %1; cvt.u32.u64 %0, t; }" : "=r"(a) : "l"(p));
    return a;
}

union HQ { __half h[4]; uint2 u; };
__device__ __forceinline__ void split4(float4 v, uint2& hi, uint2& lo) {
    HQ H, L;
    H.h[0] = __float2half_rn(v.x); L.h[0] = __float2half_rn(v.x - __half2float(H.h[0]));
    H.h[1] = __float2half_rn(v.y); L.h[1] = __float2half_rn(v.y - __half2float(H.h[1]));
    H.h[2] = __float2half_rn(v.z); L.h[2] = __float2half_rn(v.z - __half2float(H.h[2]));
    H.h[3] = __float2half_rn(v.w); L.h[3] = __float2half_rn(v.w - __half2float(H.h[3]));
    hi = H.u; lo = L.u;
}
union HP { __half h[2]; uint32_t u; };
__device__ __forceinline__ void split2(float x0, float x1, uint32_t& hi, uint32_t& lo) {
    HP H, L;
    H.h[0] = __float2half_rn(x0); L.h[0] = __float2half_rn(x0 - __half2float(H.h[0]));
    H.h[1] = __float2half_rn(x1); L.h[1] = __float2half_rn(x1 - __half2float(H.h[1]));
    hi = H.u; lo = L.u;
}

#define LDSM_X4(r0, r1, r2, r3, addr) \
    asm volatile("ldmatrix.sync.aligned.m8n8.x4.shared.b16 {%0,%1,%2,%3}, [%4];" \
        : "=r"(r0), "=r"(r1), "=r"(r2), "=r"(r3) : "r"(addr))

#define MMA_F16(d, a, b0v, b1v) \
    asm volatile("mma.sync.aligned.m16n8k16.row.col.f32.f16.f16.f32 " \
        "{%0,%1,%2,%3}, {%4,%5,%6,%7}, {%8,%9}, {%0,%1,%2,%3};" \
        : "+f"((d)[0]), "+f"((d)[1]), "+f"((d)[2]), "+f"((d)[3]) \
        : "r"((a)[0]), "r"((a)[1]), "r"((a)[2]), "r"((a)[3]), "r"(b0v), "r"(b1v))

#define CP_ASYNC16(dst, src) \
    asm volatile("cp.async.cg.shared.global [%0], [%1], 16;" :: "r"(dst), "l"(src))
#define CP_COMMIT()  asm volatile("cp.async.commit_group;" ::: "memory")
#define CP_WAIT1()   asm volatile("cp.async.wait_group 1;" ::: "memory")

// ================= tensor-core GEMM (mma.sync fp16, 2-term split) =========
// C[M,N] = act(A @ W^T + bias). A: fp16 split [rows][1536] (hi|lo), W: fp16 hi [rows][768].
// Virtual K = 1536 over 2 phases: (A_hi, W_hi), (A_lo, W_hi). fp32 accumulate.
// Tile 128x256, BK=64, 256 thr (8 warps, 4m x 2n, warp tile 32x128), 3-stage cp.async.
#define STAGES 3
#define STG_BYTES 49152               // 16KB A + 32KB B
#define GEMM_SMEM (STAGES * STG_BYTES + 128)
#define NCHUNK 24

template<int ACT, int SPLIT>
__global__ __launch_bounds__(256, 1)
void gemm_tc(const __half* __restrict__ A, const __half* __restrict__ W,
             const float* __restrict__ bias, float* __restrict__ C,
             __half* __restrict__ Cs, int M, int N)
{
    extern __shared__ char smraw[];
    const uint32_t sbase = (smem_u32(smraw) + 127u) & ~127u;

    const int tid  = threadIdx.x;
    const int lane = tid & 31;
    const int wid  = tid >> 5;
    const int wm   = wid & 3;          // m offset 32*wm
    const int wn   = wid >> 2;         // n offset 128*wn
    const int row0 = blockIdx.y * 128;
    const int col0 = blockIdx.x * 256;

    // ---- A loader: thread covers row tid/2, 64B half (tid&1) ----
    const int lrow  = tid >> 1;
    const int lhalf = tid & 1;
    const int arow  = min(row0 + lrow, M - 1);      // clamp: extra rows never stored
    const __half* gA = A + (size_t)arow * DIM2;
    uint32_t sdstA[4];
    {
        const uint32_t rb = (uint32_t)lrow * 128u;
        const uint32_t xv = ((uint32_t)lrow & 7u) << 4;
#pragma unroll
        for (int i = 0; i < 4; i++)
            sdstA[i] = rb + ((((uint32_t)lhalf) * 64u + (uint32_t)i * 16u) ^ xv);
    }
    // ---- B loader: thread covers W row col0+tid, full 128B ----
    const __half* gB = W + (size_t)(col0 + tid) * DIM;
    uint32_t sdstB[8];
    {
        const uint32_t rb = (uint32_t)tid * 128u;
        const uint32_t xv = ((uint32_t)tid & 7u) << 4;
#pragma unroll
        for (int i = 0; i < 8; i++)
            sdstB[i] = rb + (((uint32_t)i * 16u) ^ xv);
    }

    // ---- ldmatrix per-lane precompute ----
    const int l8 = lane & 7;
    const int mi = lane >> 3;
    uint32_t aoff[2], ax[2];
#pragma unroll
    for (int s = 0; s < 2; s++) {
        int r = wm * 32 + s * 16 + (mi & 1) * 8 + l8;
        aoff[s] = (uint32_t)r * 128u;
        ax[s]   = ((uint32_t)r & 7u) << 4;
    }
    const uint32_t akb = (uint32_t)(mi >> 1) * 16u;
    uint32_t boff[8], bx[8];
#pragma unroll
    for (int j = 0; j < 8; j++) {
        int r = wn * 128 + j * 16 + (mi >> 1) * 8 + l8;
        boff[j] = (uint32_t)r * 128u;
        bx[j]   = ((uint32_t)r & 7u) << 4;
    }
    const uint32_t bkb = (uint32_t)(mi & 1) * 16u;

    float acc[2][16][4];
#pragma unroll
    for (int s = 0; s < 2; s++)
#pragma unroll
        for (int j = 0; j < 16; j++)
#pragma unroll
            for (int q = 0; q < 4; q++) acc[s][j][q] = 0.f;

    // ---- stage issue: chunk c -> phase p=c/12 (A hi/lo), kc=c%12 ----
    auto issue = [&](int c) {
        const int p  = c / 12;
        const int kc = c - p * 12;
        const int acol = p * DIM + kc * 64 + lhalf * 32;
        const int bcol = kc * 64;
        const uint32_t Ab = sbase + (uint32_t)(c % STAGES) * STG_BYTES;
        const uint32_t Bb = Ab + 16384u;
        const __half* pa = gA + acol;
        const __half* pb = gB + bcol;
#pragma unroll
        for (int i = 0; i < 4; i++) CP_ASYNC16(Ab + sdstA[i], pa + i * 8);
#pragma unroll
        for (int i = 0; i < 8; i++) CP_ASYNC16(Bb + sdstB[i], pb + i * 8);
        CP_COMMIT();
    };

    issue(0);
    issue(1);

    for (int c = 0; c < NCHUNK; c++) {
        CP_WAIT1();
        __syncthreads();
        const uint32_t Ab = sbase + (uint32_t)(c % STAGES) * STG_BYTES;
        const uint32_t Bb = Ab + 16384u;
#pragma unroll
        for (int kk = 0; kk < 4; kk++) {
            const uint32_t kb = (uint32_t)kk * 32u;
            uint32_t a[2][4];
#pragma unroll
            for (int s = 0; s < 2; s++) {
                uint32_t ad = Ab + aoff[s] + ((kb + akb) ^ ax[s]);
                LDSM_X4(a[s][0], a[s][1], a[s][2], a[s][3], ad);
            }
#pragma unroll
            for (int j = 0; j < 8; j++) {
                uint32_t b[4];
                uint32_t bd = Bb + boff[j] + ((kb + bkb) ^ bx[j]);
                LDSM_X4(b[0], b[1], b[2], b[3], bd);
                MMA_F16(acc[0][2 * j],     a[0], b[0], b[1]);
                MMA_F16(acc[0][2 * j + 1], a[0], b[2], b[3]);
                MMA_F16(acc[1][2 * j],     a[1], b[0], b[1]);
                MMA_F16(acc[1][2 * j + 1], a[1], b[2], b[3]);
            }
        }
        if (c + 2 < NCHUNK) issue(c + 2);
    }

    // ---- epilogue ----
    const int mrow = lane >> 2;
    const int mcol = (lane & 3) * 2;
#pragma unroll
    for (int s = 0; s < 2; s++) {
        const int r1 = row0 + wm * 32 + s * 16 + mrow;
        const int r2 = r1 + 8;
#pragma unroll
        for (int j = 0; j < 16; j++) {
            const int col = col0 + wn * 128 + j * 8 + mcol;
            const float b0v = bias[col], b1v = bias[col + 1];
            float x0 = acc[s][j][0] + b0v, x1 = acc[s][j][1] + b1v;
            float y0 = acc[s][j][2] + b0v, y1 = acc[s][j][3] + b1v;
            if (ACT) { x0 = tanhf(x0); x1 = tanhf(x1); y0 = tanhf(y0); y1 = tanhf(y1); }
            if (r1 < M) {
                *(float2*)(C + (size_t)r1 * N + col) = make_float2(x0, x1);
                if (SPLIT) {
                    uint32_t hi, lo; split2(x0, x1, hi, lo);
                    __half* hrow = Cs + (size_t)r1 * DIM2;
                    *(uint32_t*)(hrow + col)       = hi;
                    *(uint32_t*)(hrow + DIM + col) = lo;
                }
            }
            if (r2 < M) {
                *(float2*)(C + (size_t)r2 * N + col) = make_float2(y0, y1);
                if (SPLIT) {
                    uint32_t hi, lo; split2(y0, y1, hi, lo);
                    __half* hrow = Cs + (size_t)r2 * DIM2;
                    *(uint32_t*)(hrow + col)       = hi;
                    *(uint32_t*)(hrow + DIM + col) = lo;
                }
            }
        }
    }
}

// ================= fused preprocessing: all splits/halves in ONE launch ==========
// task 0: smask -> g_smasks (split)   task 1: relE -> g_rels (split)
// task 2: W_sub -> g_Wsubs (half)     task 3: W_obj -> g_Wobjs (half)
// task 4: W_ih  -> g_Wihs  (half)     task 5: W_hh  -> g_Whhs  (half)
__global__ void k_prep(const float* __restrict__ smask, const float* __restrict__ relE,
                       const float* __restrict__ W_sub, const float* __restrict__ W_obj,
                       const float* __restrict__ W_ih,  const float* __restrict__ W_hh,
                       int S, int R)
{
    const int i = blockIdx.x * blockDim.x + threadIdx.x;
    const int task = blockIdx.y;
    const float* src; __half* dst; int tot; int do_split;
    switch (task) {
    case 0:  src = smask; dst = g_smasks; tot = S * 192;    do_split = 1; break;
    case 1:  src = relE;  dst = g_rels;   tot = R * 192;    do_split = 1; break;
    case 2:  src = W_sub; dst = g_Wsubs;  tot = DIM * 192;  do_split = 0; break;
    case 3:  src = W_obj; dst = g_Wobjs;  tot = DIM * 192;  do_split = 0; break;
    case 4:  src = W_ih;  dst = g_Wihs;   tot = DIM3 * 192; do_split = 0; break;
    default: src = W_hh;  dst = g_Whhs;   tot = DIM3 * 192; do_split = 0; break;
    }
    if (i >= tot) return;
    float4 v = *(const float4*)(src + (size_t)i * 4);
    if (do_split) {
        int r = i / 192, c = (i - r * 192) * 4;
        uint2 hi, lo; split4(v, hi, lo);
        __half* row = dst + (size_t)r * DIM2;
        *(uint2*)(row + c)       = hi;
        *(uint2*)(row + DIM + c) = lo;
    } else {
        HQ H;
        H.h[0] = __float2half_rn(v.x); H.h[1] = __float2half_rn(v.y);
        H.h[2] = __float2half_rn(v.z); H.h[3] = __float2half_rn(v.w);
        *(uint2*)(dst + (size_t)i * 4) = H.u;
    }
}

__global__ void k_gi_enc(const float* __restrict__ enc, const float* __restrict__ W_ih,
                         const float* __restrict__ b_ih)
{
    int j = blockIdx.x * 8 + (threadIdx.x >> 5);
    int lane = threadIdx.x & 31;
    if (j >= DIM3) return;
    const float* w = W_ih + (size_t)j * DIM;
    float s = 0.f;
#pragma unroll
    for (int k = lane * 4; k < DIM; k += 128) {
        float4 wv = *(const float4*)(w + k);
        float4 ev = *(const float4*)(enc + k);
        s += wv.x * ev.x + wv.y * ev.y + wv.z * ev.z + wv.w * ev.w;
    }
#pragma unroll
    for (int o = 16; o; o >>= 1) s += __shfl_xor_sync(0xffffffffu, s, o);
    if (lane == 0) g_gi_enc[j] = s + b_ih[j];
}

__device__ __forceinline__ float sigm(float x) { return 1.f / (1.f + __expf(-x)); }
__device__ __forceinline__ float gru1(float ir, float iz, float in_,
                                      float hr, float hz, float hn, float h) {
    float r = sigm(ir + hr);
    float z = sigm(iz + hz);
    float n = tanhf(in_ + r * hn);
    return (1.f - z) * n + z * h;
}

// r0 = GRU(enc broadcast, h=sub) -> fp16 split (consumed only by gi0 GEMM)
__global__ void k_gru_r0(int S)
{
    int i = blockIdx.x * blockDim.x + threadIdx.x;
    if (i >= S * 192) return;
    int s = i / 192, d = (i - s * 192) * 4;
    const float* gh = g_gh + (size_t)s * DIM3;
    float4 ir  = *(const float4*)(g_gi_enc + d);
    float4 iz  = *(const float4*)(g_gi_enc + DIM + d);
    float4 in_ = *(const float4*)(g_gi_enc + 2 * DIM + d);
    float4 hr  = *(const float4*)(gh + d);
    float4 hz  = *(const float4*)(gh + DIM + d);
    float4 hn  = *(const float4*)(gh + 2 * DIM + d);
    float4 hh  = *(const float4*)(g_sub + (size_t)s * DIM + d);
    float4 o;
    o.x = gru1(ir.x, iz.x, in_.x, hr.x, hz.x, hn.x, hh.x);
    o.y = gru1(ir.y, iz.y, in_.y, hr.y, hz.y, hn.y, hh.y);
    o.z = gru1(ir.z, iz.z, in_.z, hr.z, hz.z, hn.z, hh.z);
    o.w = gru1(ir.w, iz.w, in_.w, hr.w, hz.w, hn.w, hh.w);
    uint2 hi, lo; split4(o, hi, lo);
    __half* row = g_r0s + (size_t)s * DIM2;
    *(uint2*)(row + d)       = hi;
    *(uint2*)(row + DIM + d) = lo;
}

__global__ void k_init(int N)
{
    int i = blockIdx.x * blockDim.x + threadIdx.x;
    if (i < N) { g_best[i] = -1; g_seedpos[i] = -1; }
}
__global__ void k_seed(const int* __restrict__ seeds, int S, int stride)
{
    int s = blockIdx.x * blockDim.x + threadIdx.x;
    if (s >= S) return;
    int node = seeds[s];
    g_seedpos[node] = s;
    atomicMax(&g_best[node], s * stride);
}
__global__ void k_edge(const int* __restrict__ heads, const int* __restrict__ tails,
                       int E, int stride)
{
    int e = blockIdx.x * blockDim.x + threadIdx.x;
    if (e >= E) return;
    int pos = g_seedpos[heads[e]];
    int t = pos * stride + 1 + e;
    atomicMax(&g_best[tails[e]], t);
}

// rj[e] = GRU(gi0[head], ghR[type], h=rel[type]) -> fp16 split
__global__ void k_rj(const int* __restrict__ heads, const int* __restrict__ types,
                     const float* __restrict__ rel)
{
    int e = blockIdx.x;
    int h = heads[e];
    int t = types[e];
    const float* gi = g_gi0 + (size_t)h * DIM3;
    const float* gh = g_ghR + (size_t)t * DIM3;
    const float* rl = rel + (size_t)t * DIM;
    int d = threadIdx.x * 4;
    float4 ir  = *(const float4*)(gi + d);
    float4 iz  = *(const float4*)(gi + DIM + d);
    float4 in_ = *(const float4*)(gi + 2 * DIM + d);
    float4 hr  = *(const float4*)(gh + d);
    float4 hz  = *(const float4*)(gh + DIM + d);
    float4 hn  = *(const float4*)(gh + 2 * DIM + d);
    float4 hh  = *(const float4*)(rl + d);
    float4 o;
    o.x = gru1(ir.x, iz.x, in_.x, hr.x, hz.x, hn.x, hh.x);
    o.y = gru1(ir.y, iz.y, in_.y, hr.y, hz.y, hn.y, hh.y);
    o.z = gru1(ir.z, iz.z, in_.z, hr.z, hz.z, hn.z, hh.z);
    o.w = gru1(ir.w, iz.w, in_.w, hr.w, hz.w, hn.w, hh.w);
    uint2 hi, lo; split4(o, hi, lo);
    __half* row = g_rjs + (size_t)e * DIM2;
    *(uint2*)(row + d)       = hi;
    *(uint2*)(row + DIM + d) = lo;
}

__global__ void k_out(const int* __restrict__ node2node, const int* __restrict__ old_nd,
                      const float* __restrict__ defa, float* __restrict__ out, int stride)
{
    int nrow = blockIdx.x;
    int id = node2node[old_nd[nrow]];
    int b = g_best[id];
    const float* src;
    if (b < 0) {
        src = defa + (size_t)nrow * DIM;
    } else {
        int q = b / stride;
        int rem = b - q * stride;
        src = (rem == 0) ? (g_sub + (size_t)q * DIM)
                         : (g_obj + (size_t)(rem - 1) * DIM);
    }
    int d = threadIdx.x * 4;
    *(float4*)(out + (size_t)nrow * DIM + d) = *(const float4*)(src + d);
}

// ================= host =================
extern "C" void kernel_launch(void* const* d_in, const int* in_sizes, int n_in,
                              void* d_out, int out_size)
{
    const float* enc   = (const float*)d_in[0];
    const float* smask = (const float*)d_in[1];
    const int*   seeds = (const int*)  d_in[2];
    const int*   ehead = (const int*)  d_in[3];
    const int*   etail = (const int*)  d_in[4];
    const int*   etype = (const int*)  d_in[5];
    const int*   n2n   = (const int*)  d_in[6];
    const int*   oldnd = (const int*)  d_in[7];
    const float* relE  = (const float*)d_in[8];
    const float* W_sub = (const float*)d_in[9];
    const float* b_sub = (const float*)d_in[10];
    const float* W_obj = (const float*)d_in[11];
    const float* b_obj = (const float*)d_in[12];
    const float* W_ih  = (const float*)d_in[13];
    const float* W_hh  = (const float*)d_in[14];
    const float* b_ih  = (const float*)d_in[15];
    const float* b_hh  = (const float*)d_in[16];
    const float* defa  = (const float*)d_in[17];
    float* out = (float*)d_out;

    const int S = in_sizes[2];
    const int E = in_sizes[3];
    const int N = in_sizes[6];
    const int R = in_sizes[8] / DIM;
    const int stride = E + 1;

    float *p_sub, *p_gh, *p_gi0, *p_ghR, *p_obj;
    __half *p_smasks, *p_subs, *p_r0s, *p_rjs, *p_rels,
           *p_Wsubs, *p_Wobjs, *p_Wihs, *p_Whhs;
    cudaGetSymbolAddress((void**)&p_sub,    g_sub);
    cudaGetSymbolAddress((void**)&p_gh,     g_gh);
    cudaGetSymbolAddress((void**)&p_gi0,    g_gi0);
    cudaGetSymbolAddress((void**)&p_ghR,    g_ghR);
    cudaGetSymbolAddress((void**)&p_obj,    g_obj);
    cudaGetSymbolAddress((void**)&p_smasks, g_smasks);
    cudaGetSymbolAddress((void**)&p_subs,   g_subs);
    cudaGetSymbolAddress((void**)&p_r0s,    g_r0s);
    cudaGetSymbolAddress((void**)&p_rjs,    g_rjs);
    cudaGetSymbolAddress((void**)&p_rels,   g_rels);
    cudaGetSymbolAddress((void**)&p_Wsubs,  g_Wsubs);
    cudaGetSymbolAddress((void**)&p_Wobjs,  g_Wobjs);
    cudaGetSymbolAddress((void**)&p_Wihs,   g_Wihs);
    cudaGetSymbolAddress((void**)&p_Whhs,   g_Whhs);

    cudaFuncSetAttribute(gemm_tc<1,1>, cudaFuncAttributeMaxDynamicSharedMemorySize, GEMM_SMEM);
    cudaFuncSetAttribute(gemm_tc<0,0>, cudaFuncAttributeMaxDynamicSharedMemorySize, GEMM_SMEM);
    cudaFuncSetAttribute(gemm_tc<1,0>, cudaFuncAttributeMaxDynamicSharedMemorySize, GEMM_SMEM);

    // independent setup first (also shifts ncu capture slot onto a GEMM)
    k_init<<<(N + 255) / 256, 256>>>(N);
    {
        dim3 grid((DIM3 * 192 + 255) / 256, 6);
        k_prep<<<grid, 256>>>(smask, relE, W_sub, W_obj, W_ih, W_hh, S, R);
    }
    k_gi_enc<<<(DIM3 + 7) / 8, 256>>>(enc, W_ih, b_ih);
    k_seed<<<(S + 255) / 256, 256>>>(seeds, S, stride);
    k_edge<<<(E + 255) / 256, 256>>>(ehead, etail, E, stride);

    // sub = tanh(mask @ W_sub^T + b_sub)      [S,768], + split copy   <-- ncu capture slot
    gemm_tc<1,1><<<dim3(DIM / 256, S / 128), 256, GEMM_SMEM>>>(
        p_smasks, p_Wsubs, b_sub, p_sub, p_subs, S, DIM);
    // gh = sub @ W_hh^T + b_hh                [S,2304]
    gemm_tc<0,0><<<dim3(DIM3 / 256, S / 128), 256, GEMM_SMEM>>>(
        p_subs, p_Whhs, b_hh, p_gh, (__half*)0, S, DIM3);
    // r0 = GRU(enc, sub) -> fp16 split
    k_gru_r0<<<(S * 192 + 255) / 256, 256>>>(S);
    // gi0 = r0 @ W_ih^T + b_ih                [S,2304]
    gemm_tc<0,0><<<dim3(DIM3 / 256, S / 128), 256, GEMM_SMEM>>>(
        p_r0s, p_Wihs, b_ih, p_gi0, (__half*)0, S, DIM3);
    // ghR = rel_emb @ W_hh^T + b_hh           [R,2304]
    gemm_tc<0,0><<<dim3(DIM3 / 256, (R + 127) / 128), 256, GEMM_SMEM>>>(
        p_rels, p_Whhs, b_hh, p_ghR, (__half*)0, R, DIM3);

    // rj[e] = GRU(gi0[head], rel[type]) -> fp16 split
    k_rj<<<E, 192>>>(ehead, etype, relE);
    // obj = tanh(rj @ W_obj^T + b_obj)        [E,768]  (dominant GEMM)
    gemm_tc<1,0><<<dim3(DIM / 256, E / 128), 256, GEMM_SMEM>>>(
        p_rjs, p_Wobjs, b_obj, p_obj, (__half*)0, E, DIM);

    k_out<<<N, 192>>>(n2n, oldnd, defa, out, stride);
}

// round 14
// speedup vs baseline: 1.2803x; 1.2803x over previous
#include <cuda_runtime.h>
#include <cuda_fp16.h>
#include <stdint.h>

#define DIM  768
#define DIM2 1536
#define DIM3 2304
#define MAX_S 2048
#define MAX_E 32768
#define MAX_N 100000
#define MAX_R 1000

// ---------------- fp32 scratch ----------------
__device__ float g_sub [MAX_S * DIM];
__device__ float g_obj [MAX_E * DIM];
__device__ float g_gi_enc[DIM3];
__device__ int   g_best[MAX_N];
__device__ int   g_seedpos[MAX_N];

// ---- fp16 gate pre-activation buffers (GEMM outputs consumed by GRU kernels) ----
__device__ __half g_ghH  [MAX_S * DIM3];
__device__ __half g_gi0H [MAX_S * DIM3];
__device__ __half g_ghRH [MAX_R * DIM3];

// ---- fp16 A-operand scratch: [rows][1536], hi in [0,768), lo in [768,1536) ----
__device__ __half g_smasks[MAX_S * DIM2];
__device__ __half g_subs  [MAX_S * DIM2];
__device__ __half g_r0s   [MAX_S * DIM2];
__device__ __half g_rjs   [(size_t)MAX_E * DIM2];
__device__ __half g_rels  [MAX_R * DIM2];
// ---- fp16 W-operand scratch (hi only): [rows][768] ----
__device__ __half g_Wsubs [DIM  * DIM];
__device__ __half g_Wobjs [DIM  * DIM];
__device__ __half g_Wihs  [DIM3 * DIM];
__device__ __half g_Whhs  [DIM3 * DIM];

// ---------------- helpers ----------------
__device__ __forceinline__ uint32_t smem_u32(const void* p) {
    uint32_t a;
    asm("{ .reg .u64 t; cvta.to.shared.u64 t, %1; cvt.u32.u64 %0, t; }" : "=r"(a) : "l"(p));
    return a;
}

union HQ { __half h[4]; uint2 u; };
__device__ __forceinline__ void split4(float4 v, uint2& hi, uint2& lo) {
    HQ H, L;
    H.h[0] = __float2half_rn(v.x); L.h[0] = __float2half_rn(v.x - __half2float(H.h[0]));
    H.h[1] = __float2half_rn(v.y); L.h[1] = __float2half_rn(v.y - __half2float(H.h[1]));
    H.h[2] = __float2half_rn(v.z); L.h[2] = __float2half_rn(v.z - __half2float(H.h[2]));
    H.h[3] = __float2half_rn(v.w); L.h[3] = __float2half_rn(v.w - __half2float(H.h[3]));
    hi = H.u; lo = L.u;
}
union HP { __half h[2]; uint32_t u; };
__device__ __forceinline__ void split2(float x0, float x1, uint32_t& hi, uint32_t& lo) {
    HP H, L;
    H.h[0] = __float2half_rn(x0); L.h[0] = __float2half_rn(x0 - __half2float(H.h[0]));
    H.h[1] = __float2half_rn(x1); L.h[1] = __float2half_rn(x1 - __half2float(H.h[1]));
    hi = H.u; lo = L.u;
}
// load 4 consecutive halves -> float4
__device__ __forceinline__ float4 ld4h(const __half* p) {
    uint2 u = *(const uint2*)p;
    float2 f0 = __half22float2(*(__half2*)&u.x);
    float2 f1 = __half22float2(*(__half2*)&u.y);
    return make_float4(f0.x, f0.y, f1.x, f1.y);
}

#define LDSM_X4(r0, r1, r2, r3, addr) \
    asm volatile("ldmatrix.sync.aligned.m8n8.x4.shared.b16 {%0,%1,%2,%3}, [%4];" \
        : "=r"(r0), "=r"(r1), "=r"(r2), "=r"(r3) : "r"(addr))

#define MMA_F16(d, a, b0v, b1v) \
    asm volatile("mma.sync.aligned.m16n8k16.row.col.f32.f16.f16.f32 " \
        "{%0,%1,%2,%3}, {%4,%5,%6,%7}, {%8,%9}, {%0,%1,%2,%3};" \
        : "+f"((d)[0]), "+f"((d)[1]), "+f"((d)[2]), "+f"((d)[3]) \
        : "r"((a)[0]), "r"((a)[1]), "r"((a)[2]), "r"((a)[3]), "r"(b0v), "r"(b1v))

#define CP_ASYNC16(dst, src) \
    asm volatile("cp.async.cg.shared.global [%0], [%1], 16;" :: "r"(dst), "l"(src))
#define CP_COMMIT()  asm volatile("cp.async.commit_group;" ::: "memory")
#define CP_WAIT1()   asm volatile("cp.async.wait_group 1;" ::: "memory")

// ================= tensor-core GEMM (mma.sync fp16, 2-term split) =========
// C[M,N] = act(A @ W^T + bias). A: fp16 split [rows][1536] (hi|lo), W: fp16 hi [rows][768].
// Virtual K = 1536 over 2 phases: (A_hi, W_hi), (A_lo, W_hi). fp32 accumulate.
// Tile 128x128, BK=64, 256 thr (8 warps, 4m x 2n, warp tile 32x64), 3-stage cp.async, occ 2.
#define STAGES 3
#define STG_BYTES 32768
#define GEMM_SMEM (STAGES * STG_BYTES + 128)
#define NCHUNK 24

template<int ACT, int SPLIT, int HOUT>
__global__ __launch_bounds__(256, 2)
void gemm_tc(const __half* __restrict__ A, const __half* __restrict__ W,
             const float* __restrict__ bias, float* __restrict__ C,
             __half* __restrict__ Cs, __half* __restrict__ Ch, int M, int N)
{
    extern __shared__ char smraw[];
    const uint32_t sbase = (smem_u32(smraw) + 127u) & ~127u;

    const int tid  = threadIdx.x;
    const int lane = tid & 31;
    const int wid  = tid >> 5;
    const int wm   = wid & 3;          // m offset 32*wm
    const int wn   = wid >> 2;         // n offset 64*wn
    const int row0 = blockIdx.y * 128;
    const int col0 = blockIdx.x * 128;

    // ---- loader precompute: thread covers row tid/2, 64B half (tid&1) ----
    const int lrow  = tid >> 1;
    const int lhalf = tid & 1;
    const int arow  = min(row0 + lrow, M - 1);      // clamp: extra rows never stored
    const __half* gA = A + (size_t)arow * DIM2;
    const __half* gB = W + (size_t)(col0 + lrow) * DIM;
    uint32_t sdst[4];
    {
        const uint32_t rb = (uint32_t)lrow * 128u;
        const uint32_t xv = ((uint32_t)lrow & 7u) << 4;
#pragma unroll
        for (int i = 0; i < 4; i++)
            sdst[i] = rb + ((((uint32_t)lhalf) * 64u + (uint32_t)i * 16u) ^ xv);
    }

    // ---- ldmatrix per-lane precompute ----
    const int l8 = lane & 7;
    const int mi = lane >> 3;
    uint32_t aoff[2], ax[2];
#pragma unroll
    for (int s = 0; s < 2; s++) {
        int r = wm * 32 + s * 16 + (mi & 1) * 8 + l8;
        aoff[s] = (uint32_t)r * 128u;
        ax[s]   = ((uint32_t)r & 7u) << 4;
    }
    const uint32_t akb = (uint32_t)(mi >> 1) * 16u;
    uint32_t boff[4], bx[4];
#pragma unroll
    for (int j = 0; j < 4; j++) {
        int r = wn * 64 + j * 16 + (mi >> 1) * 8 + l8;
        boff[j] = (uint32_t)r * 128u;
        bx[j]   = ((uint32_t)r & 7u) << 4;
    }
    const uint32_t bkb = (uint32_t)(mi & 1) * 16u;

    float acc[2][8][4];
#pragma unroll
    for (int s = 0; s < 2; s++)
#pragma unroll
        for (int j = 0; j < 8; j++)
#pragma unroll
            for (int q = 0; q < 4; q++) acc[s][j][q] = 0.f;

    // ---- stage issue: chunk c -> phase p=c/12 (A hi/lo), kc=c%12 ----
    auto issue = [&](int c) {
        const int p  = c / 12;
        const int kc = c - p * 12;
        const int acol = p * DIM + kc * 64 + lhalf * 32;
        const int bcol = kc * 64 + lhalf * 32;
        const uint32_t Ab = sbase + (uint32_t)(c % STAGES) * STG_BYTES;
        const uint32_t Bb = Ab + 16384u;
        const __half* pa = gA + acol;
        const __half* pb = gB + bcol;
#pragma unroll
        for (int i = 0; i < 4; i++) CP_ASYNC16(Ab + sdst[i], pa + i * 8);
#pragma unroll
        for (int i = 0; i < 4; i++) CP_ASYNC16(Bb + sdst[i], pb + i * 8);
        CP_COMMIT();
    };

    issue(0);
    issue(1);

    for (int c = 0; c < NCHUNK; c++) {
        CP_WAIT1();
        __syncthreads();
        const uint32_t Ab = sbase + (uint32_t)(c % STAGES) * STG_BYTES;
        const uint32_t Bb = Ab + 16384u;
#pragma unroll
        for (int kk = 0; kk < 4; kk++) {
            const uint32_t kb = (uint32_t)kk * 32u;
            uint32_t a[2][4];
#pragma unroll
            for (int s = 0; s < 2; s++) {
                uint32_t ad = Ab + aoff[s] + ((kb + akb) ^ ax[s]);
                LDSM_X4(a[s][0], a[s][1], a[s][2], a[s][3], ad);
            }
#pragma unroll
            for (int j = 0; j < 4; j++) {
                uint32_t b[4];
                uint32_t bd = Bb + boff[j] + ((kb + bkb) ^ bx[j]);
                LDSM_X4(b[0], b[1], b[2], b[3], bd);
                MMA_F16(acc[0][2 * j],     a[0], b[0], b[1]);
                MMA_F16(acc[0][2 * j + 1], a[0], b[2], b[3]);
                MMA_F16(acc[1][2 * j],     a[1], b[0], b[1]);
                MMA_F16(acc[1][2 * j + 1], a[1], b[2], b[3]);
            }
        }
        if (c + 2 < NCHUNK) issue(c + 2);
    }

    // ---- epilogue ----
    const int mrow = lane >> 2;
    const int mcol = (lane & 3) * 2;
#pragma unroll
    for (int s = 0; s < 2; s++) {
        const int r1 = row0 + wm * 32 + s * 16 + mrow;
        const int r2 = r1 + 8;
#pragma unroll
        for (int j = 0; j < 8; j++) {
            const int col = col0 + wn * 64 + j * 8 + mcol;
            const float b0v = bias[col], b1v = bias[col + 1];
            float x0 = acc[s][j][0] + b0v, x1 = acc[s][j][1] + b1v;
            float y0 = acc[s][j][2] + b0v, y1 = acc[s][j][3] + b1v;
            if (ACT) { x0 = tanhf(x0); x1 = tanhf(x1); y0 = tanhf(y0); y1 = tanhf(y1); }
            if (r1 < M) {
                if (HOUT) {
                    HP P; P.h[0] = __float2half_rn(x0); P.h[1] = __float2half_rn(x1);
                    *(uint32_t*)(Ch + (size_t)r1 * N + col) = P.u;
                } else {
                    *(float2*)(C + (size_t)r1 * N + col) = make_float2(x0, x1);
                }
                if (SPLIT) {
                    uint32_t hi, lo; split2(x0, x1, hi, lo);
                    __half* hrow = Cs + (size_t)r1 * DIM2;
                    *(uint32_t*)(hrow + col)       = hi;
                    *(uint32_t*)(hrow + DIM + col) = lo;
                }
            }
            if (r2 < M) {
                if (HOUT) {
                    HP P; P.h[0] = __float2half_rn(y0); P.h[1] = __float2half_rn(y1);
                    *(uint32_t*)(Ch + (size_t)r2 * N + col) = P.u;
                } else {
                    *(float2*)(C + (size_t)r2 * N + col) = make_float2(y0, y1);
                }
                if (SPLIT) {
                    uint32_t hi, lo; split2(y0, y1, hi, lo);
                    __half* hrow = Cs + (size_t)r2 * DIM2;
                    *(uint32_t*)(hrow + col)       = hi;
                    *(uint32_t*)(hrow + DIM + col) = lo;
                }
            }
        }
    }
}

// ================= fused preprocessing: all splits/halves in ONE launch ==========
__global__ void k_prep(const float* __restrict__ smask, const float* __restrict__ relE,
                       const float* __restrict__ W_sub, const float* __restrict__ W_obj,
                       const float* __restrict__ W_ih,  const float* __restrict__ W_hh,
                       int S, int R)
{
    const int i = blockIdx.x * blockDim.x + threadIdx.x;
    const int task = blockIdx.y;
    const float* src; __half* dst; int tot; int do_split;
    switch (task) {
    case 0:  src = smask; dst = g_smasks; tot = S * 192;    do_split = 1; break;
    case 1:  src = relE;  dst = g_rels;   tot = R * 192;    do_split = 1; break;
    case 2:  src = W_sub; dst = g_Wsubs;  tot = DIM * 192;  do_split = 0; break;
    case 3:  src = W_obj; dst = g_Wobjs;  tot = DIM * 192;  do_split = 0; break;
    case 4:  src = W_ih;  dst = g_Wihs;   tot = DIM3 * 192; do_split = 0; break;
    default: src = W_hh;  dst = g_Whhs;   tot = DIM3 * 192; do_split = 0; break;
    }
    if (i >= tot) return;
    float4 v = *(const float4*)(src + (size_t)i * 4);
    if (do_split) {
        int r = i / 192, c = (i - r * 192) * 4;
        uint2 hi, lo; split4(v, hi, lo);
        __half* row = dst + (size_t)r * DIM2;
        *(uint2*)(row + c)       = hi;
        *(uint2*)(row + DIM + c) = lo;
    } else {
        HQ H;
        H.h[0] = __float2half_rn(v.x); H.h[1] = __float2half_rn(v.y);
        H.h[2] = __float2half_rn(v.z); H.h[3] = __float2half_rn(v.w);
        *(uint2*)(dst + (size_t)i * 4) = H.u;
    }
}

__global__ void k_gi_enc(const float* __restrict__ enc, const float* __restrict__ W_ih,
                         const float* __restrict__ b_ih)
{
    int j = blockIdx.x * 8 + (threadIdx.x >> 5);
    int lane = threadIdx.x & 31;
    if (j >= DIM3) return;
    const float* w = W_ih + (size_t)j * DIM;
    float s = 0.f;
#pragma unroll
    for (int k = lane * 4; k < DIM; k += 128) {
        float4 wv = *(const float4*)(w + k);
        float4 ev = *(const float4*)(enc + k);
        s += wv.x * ev.x + wv.y * ev.y + wv.z * ev.z + wv.w * ev.w;
    }
#pragma unroll
    for (int o = 16; o; o >>= 1) s += __shfl_xor_sync(0xffffffffu, s, o);
    if (lane == 0) g_gi_enc[j] = s + b_ih[j];
}

__device__ __forceinline__ float sigm(float x) { return 1.f / (1.f + __expf(-x)); }
__device__ __forceinline__ float gru1(float ir, float iz, float in_,
                                      float hr, float hz, float hn, float h) {
    float r = sigm(ir + hr);
    float z = sigm(iz + hz);
    float n = tanhf(in_ + r * hn);
    return (1.f - z) * n + z * h;
}

// r0 = GRU(enc broadcast, h=sub) -> fp16 split (consumed only by gi0 GEMM)
__global__ void k_gru_r0(int S)
{
    int i = blockIdx.x * blockDim.x + threadIdx.x;
    if (i >= S * 192) return;
    int s = i / 192, d = (i - s * 192) * 4;
    const __half* gh = g_ghH + (size_t)s * DIM3;
    float4 ir  = *(const float4*)(g_gi_enc + d);
    float4 iz  = *(const float4*)(g_gi_enc + DIM + d);
    float4 in_ = *(const float4*)(g_gi_enc + 2 * DIM + d);
    float4 hr  = ld4h(gh + d);
    float4 hz  = ld4h(gh + DIM + d);
    float4 hn  = ld4h(gh + 2 * DIM + d);
    float4 hh  = *(const float4*)(g_sub + (size_t)s * DIM + d);
    float4 o;
    o.x = gru1(ir.x, iz.x, in_.x, hr.x, hz.x, hn.x, hh.x);
    o.y = gru1(ir.y, iz.y, in_.y, hr.y, hz.y, hn.y, hh.y);
    o.z = gru1(ir.z, iz.z, in_.z, hr.z, hz.z, hn.z, hh.z);
    o.w = gru1(ir.w, iz.w, in_.w, hr.w, hz.w, hn.w, hh.w);
    uint2 hi, lo; split4(o, hi, lo);
    __half* row = g_r0s + (size_t)s * DIM2;
    *(uint2*)(row + d)       = hi;
    *(uint2*)(row + DIM + d) = lo;
}

__global__ void k_init(int N)
{
    int i = blockIdx.x * blockDim.x + threadIdx.x;
    if (i < N) { g_best[i] = -1; g_seedpos[i] = -1; }
}
__global__ void k_seed(const int* __restrict__ seeds, int S, int stride)
{
    int s = blockIdx.x * blockDim.x + threadIdx.x;
    if (s >= S) return;
    int node = seeds[s];
    g_seedpos[node] = s;
    atomicMax(&g_best[node], s * stride);
}
__global__ void k_edge(const int* __restrict__ heads, const int* __restrict__ tails,
                       int E, int stride)
{
    int e = blockIdx.x * blockDim.x + threadIdx.x;
    if (e >= E) return;
    int pos = g_seedpos[heads[e]];
    int t = pos * stride + 1 + e;
    atomicMax(&g_best[tails[e]], t);
}

// rj[e] = GRU(gi0[head], ghR[type], h=rel[type]) -> fp16 split
__global__ void k_rj(const int* __restrict__ heads, const int* __restrict__ types,
                     const float* __restrict__ rel)
{
    int e = blockIdx.x;
    int h = heads[e];
    int t = types[e];
    const __half* gi = g_gi0H + (size_t)h * DIM3;
    const __half* gh = g_ghRH + (size_t)t * DIM3;
    const float*  rl = rel + (size_t)t * DIM;
    int d = threadIdx.x * 4;
    float4 ir  = ld4h(gi + d);
    float4 iz  = ld4h(gi + DIM + d);
    float4 in_ = ld4h(gi + 2 * DIM + d);
    float4 hr  = ld4h(gh + d);
    float4 hz  = ld4h(gh + DIM + d);
    float4 hn  = ld4h(gh + 2 * DIM + d);
    float4 hh  = *(const float4*)(rl + d);
    float4 o;
    o.x = gru1(ir.x, iz.x, in_.x, hr.x, hz.x, hn.x, hh.x);
    o.y = gru1(ir.y, iz.y, in_.y, hr.y, hz.y, hn.y, hh.y);
    o.z = gru1(ir.z, iz.z, in_.z, hr.z, hz.z, hn.z, hh.z);
    o.w = gru1(ir.w, iz.w, in_.w, hr.w, hz.w, hn.w, hh.w);
    uint2 hi, lo; split4(o, hi, lo);
    __half* row = g_rjs + (size_t)e * DIM2;
    *(uint2*)(row + d)       = hi;
    *(uint2*)(row + DIM + d) = lo;
}

__global__ void k_out(const int* __restrict__ node2node, const int* __restrict__ old_nd,
                      const float* __restrict__ defa, float* __restrict__ out, int stride)
{
    int nrow = blockIdx.x;
    int id = node2node[old_nd[nrow]];
    int b = g_best[id];
    const float* src;
    if (b < 0) {
        src = defa + (size_t)nrow * DIM;
    } else {
        int q = b / stride;
        int rem = b - q * stride;
        src = (rem == 0) ? (g_sub + (size_t)q * DIM)
                         : (g_obj + (size_t)(rem - 1) * DIM);
    }
    int d = threadIdx.x * 4;
    *(float4*)(out + (size_t)nrow * DIM + d) = *(const float4*)(src + d);
}

// ================= host =================
extern "C" void kernel_launch(void* const* d_in, const int* in_sizes, int n_in,
                              void* d_out, int out_size)
{
    const float* enc   = (const float*)d_in[0];
    const float* smask = (const float*)d_in[1];
    const int*   seeds = (const int*)  d_in[2];
    const int*   ehead = (const int*)  d_in[3];
    const int*   etail = (const int*)  d_in[4];
    const int*   etype = (const int*)  d_in[5];
    const int*   n2n   = (const int*)  d_in[6];
    const int*   oldnd = (const int*)  d_in[7];
    const float* relE  = (const float*)d_in[8];
    const float* W_sub = (const float*)d_in[9];
    const float* b_sub = (const float*)d_in[10];
    const float* W_obj = (const float*)d_in[11];
    const float* b_obj = (const float*)d_in[12];
    const float* W_ih  = (const float*)d_in[13];
    const float* W_hh  = (const float*)d_in[14];
    const float* b_ih  = (const float*)d_in[15];
    const float* b_hh  = (const float*)d_in[16];
    const float* defa  = (const float*)d_in[17];
    float* out = (float*)d_out;

    const int S = in_sizes[2];
    const int E = in_sizes[3];
    const int N = in_sizes[6];
    const int R = in_sizes[8] / DIM;
    const int stride = E + 1;

    float *p_sub, *p_obj;
    __half *p_ghH, *p_gi0H, *p_ghRH;
    __half *p_smasks, *p_subs, *p_r0s, *p_rjs, *p_rels,
           *p_Wsubs, *p_Wobjs, *p_Wihs, *p_Whhs;
    cudaGetSymbolAddress((void**)&p_sub,    g_sub);
    cudaGetSymbolAddress((void**)&p_obj,    g_obj);
    cudaGetSymbolAddress((void**)&p_ghH,    g_ghH);
    cudaGetSymbolAddress((void**)&p_gi0H,   g_gi0H);
    cudaGetSymbolAddress((void**)&p_ghRH,   g_ghRH);
    cudaGetSymbolAddress((void**)&p_smasks, g_smasks);
    cudaGetSymbolAddress((void**)&p_subs,   g_subs);
    cudaGetSymbolAddress((void**)&p_r0s,    g_r0s);
    cudaGetSymbolAddress((void**)&p_rjs,    g_rjs);
    cudaGetSymbolAddress((void**)&p_rels,   g_rels);
    cudaGetSymbolAddress((void**)&p_Wsubs,  g_Wsubs);
    cudaGetSymbolAddress((void**)&p_Wobjs,  g_Wobjs);
    cudaGetSymbolAddress((void**)&p_Wihs,   g_Wihs);
    cudaGetSymbolAddress((void**)&p_Whhs,   g_Whhs);

    cudaFuncSetAttribute(gemm_tc<1,1,0>, cudaFuncAttributeMaxDynamicSharedMemorySize, GEMM_SMEM);
    cudaFuncSetAttribute(gemm_tc<0,0,1>, cudaFuncAttributeMaxDynamicSharedMemorySize, GEMM_SMEM);
    cudaFuncSetAttribute(gemm_tc<1,0,0>, cudaFuncAttributeMaxDynamicSharedMemorySize, GEMM_SMEM);

    // independent setup first (also shifts ncu capture slot onto a GEMM)
    k_init<<<(N + 255) / 256, 256>>>(N);
    {
        dim3 grid((DIM3 * 192 + 255) / 256, 6);
        k_prep<<<grid, 256>>>(smask, relE, W_sub, W_obj, W_ih, W_hh, S, R);
    }
    k_gi_enc<<<(DIM3 + 7) / 8, 256>>>(enc, W_ih, b_ih);
    k_seed<<<(S + 255) / 256, 256>>>(seeds, S, stride);
    k_edge<<<(E + 255) / 256, 256>>>(ehead, etail, E, stride);

    // sub = tanh(mask @ W_sub^T + b_sub)      [S,768] fp32 + split copy
    gemm_tc<1,1,0><<<dim3(DIM / 128, S / 128), 256, GEMM_SMEM>>>(
        p_smasks, p_Wsubs, b_sub, p_sub, p_subs, (__half*)0, S, DIM);
    // gh = sub @ W_hh^T + b_hh                [S,2304] fp16 out
    gemm_tc<0,0,1><<<dim3(DIM3 / 128, S / 128), 256, GEMM_SMEM>>>(
        p_subs, p_Whhs, b_hh, (float*)0, (__half*)0, p_ghH, S, DIM3);
    // r0 = GRU(enc, sub) -> fp16 split
    k_gru_r0<<<(S * 192 + 255) / 256, 256>>>(S);
    // gi0 = r0 @ W_ih^T + b_ih                [S,2304] fp16 out
    gemm_tc<0,0,1><<<dim3(DIM3 / 128, S / 128), 256, GEMM_SMEM>>>(
        p_r0s, p_Wihs, b_ih, (float*)0, (__half*)0, p_gi0H, S, DIM3);
    // ghR = rel_emb @ W_hh^T + b_hh           [R,2304] fp16 out
    gemm_tc<0,0,1><<<dim3(DIM3 / 128, (R + 127) / 128), 256, GEMM_SMEM>>>(
        p_rels, p_Whhs, b_hh, (float*)0, (__half*)0, p_ghRH, R, DIM3);

    // rj[e] = GRU(gi0[head], rel[type]) -> fp16 split
    k_rj<<<E, 192>>>(ehead, etype, relE);
    // obj = tanh(rj @ W_obj^T + b_obj)        [E,768] fp32 (dominant GEMM)
    gemm_tc<1,0,0><<<dim3(DIM / 128, E / 128), 256, GEMM_SMEM>>>(
        p_rjs, p_Wobjs, b_obj, p_obj, (__half*)0, (__half*)0, E, DIM);

    k_out<<<N, 192>>>(n2n, oldnd, defa, out, stride);
}

// round 15
// speedup vs baseline: 1.7814x; 1.3913x over previous
#include <cuda_runtime.h>
#include <cuda_fp16.h>
#include <stdint.h>

#define DIM  768
#define DIM3 2304
#define MAX_S 2048
#define MAX_E 32768
#define MAX_N 100000
#define MAX_R 1000

// ---------------- fp32 scratch ----------------
__device__ float g_sub [MAX_S * DIM];
__device__ float g_obj [MAX_E * DIM];
__device__ float g_gi_enc[DIM3];
__device__ int   g_best[MAX_N];
__device__ int   g_seedpos[MAX_N];

// ---- fp16 gate pre-activation buffers (GEMM outputs consumed by GRU kernels) ----
__device__ __half g_ghH  [MAX_S * DIM3];
__device__ __half g_gi0H [MAX_S * DIM3];
__device__ __half g_ghRH [MAX_R * DIM3];

// ---- fp16 A-operand scratch: plain [rows][768] ----
__device__ __half g_smasks[MAX_S * DIM];
__device__ __half g_subs  [MAX_S * DIM];
__device__ __half g_r0s   [MAX_S * DIM];
__device__ __half g_rjs   [(size_t)MAX_E * DIM];
__device__ __half g_rels  [MAX_R * DIM];
// ---- fp16 W-operand scratch: [rows][768] ----
__device__ __half g_Wsubs [DIM  * DIM];
__device__ __half g_Wobjs [DIM  * DIM];
__device__ __half g_Wihs  [DIM3 * DIM];
__device__ __half g_Whhs  [DIM3 * DIM];

// ---------------- helpers ----------------
__device__ __forceinline__ uint32_t smem_u32(const void* p) {
    uint32_t a;
    asm("{ .reg .u64 t; cvta.to.shared.u64 t, %1; cvt.u32.u64 %0, t; }" : "=r"(a) : "l"(p));
    return a;
}

union HQ { __half h[4]; uint2 u; };
__device__ __forceinline__ uint2 pack4(float4 v) {
    HQ H;
    H.h[0] = __float2half_rn(v.x); H.h[1] = __float2half_rn(v.y);
    H.h[2] = __float2half_rn(v.z); H.h[3] = __float2half_rn(v.w);
    return H.u;
}
union HP { __half h[2]; uint32_t u; };
__device__ __forceinline__ uint32_t pack2(float x0, float x1) {
    HP P; P.h[0] = __float2half_rn(x0); P.h[1] = __float2half_rn(x1);
    return P.u;
}
// load 4 consecutive halves -> float4
__device__ __forceinline__ float4 ld4h(const __half* p) {
    uint2 u = *(const uint2*)p;
    float2 f0 = __half22float2(*(__half2*)&u.x);
    float2 f1 = __half22float2(*(__half2*)&u.y);
    return make_float4(f0.x, f0.y, f1.x, f1.y);
}

#define LDSM_X4(r0, r1, r2, r3, addr) \
    asm volatile("ldmatrix.sync.aligned.m8n8.x4.shared.b16 {%0,%1,%2,%3}, [%4];" \
        : "=r"(r0), "=r"(r1), "=r"(r2), "=r"(r3) : "r"(addr))

#define MMA_F16(d, a, b0v, b1v) \
    asm volatile("mma.sync.aligned.m16n8k16.row.col.f32.f16.f16.f32 " \
        "{%0,%1,%2,%3}, {%4,%5,%6,%7}, {%8,%9}, {%0,%1,%2,%3};" \
        : "+f"((d)[0]), "+f"((d)[1]), "+f"((d)[2]), "+f"((d)[3]) \
        : "r"((a)[0]), "r"((a)[1]), "r"((a)[2]), "r"((a)[3]), "r"(b0v), "r"(b1v))

#define CP_ASYNC16(dst, src) \
    asm volatile("cp.async.cg.shared.global [%0], [%1], 16;" :: "r"(dst), "l"(src))
#define CP_COMMIT()  asm volatile("cp.async.commit_group;" ::: "memory")
#define CP_WAIT1()   asm volatile("cp.async.wait_group 1;" ::: "memory")

// ================= tensor-core GEMM (mma.sync fp16, single pass, K=768) =========
// C[M,N] = act(A @ W^T + bias). A,W: fp16 [rows][768]. fp32 accumulate.
// Tile 128x128, BK=64, 256 thr (8 warps, 4m x 2n, warp tile 32x64), 3-stage cp.async, occ 2.
#define STAGES 3
#define STG_BYTES 32768
#define GEMM_SMEM (STAGES * STG_BYTES + 128)
#define NCHUNK 12

template<int ACT, int SPLIT, int HOUT>
__global__ __launch_bounds__(256, 2)
void gemm_tc(const __half* __restrict__ A, const __half* __restrict__ W,
             const float* __restrict__ bias, float* __restrict__ C,
             __half* __restrict__ Cs, __half* __restrict__ Ch, int M, int N)
{
    extern __shared__ char smraw[];
    const uint32_t sbase = (smem_u32(smraw) + 127u) & ~127u;

    const int tid  = threadIdx.x;
    const int lane = tid & 31;
    const int wid  = tid >> 5;
    const int wm   = wid & 3;          // m offset 32*wm
    const int wn   = wid >> 2;         // n offset 64*wn
    const int row0 = blockIdx.y * 128;
    const int col0 = blockIdx.x * 128;

    // ---- loader precompute: thread covers row tid/2, 64B half (tid&1) ----
    const int lrow  = tid >> 1;
    const int lhalf = tid & 1;
    const int arow  = min(row0 + lrow, M - 1);      // clamp: extra rows never stored
    const __half* gA = A + (size_t)arow * DIM;
    const __half* gB = W + (size_t)(col0 + lrow) * DIM;
    uint32_t sdst[4];
    {
        const uint32_t rb = (uint32_t)lrow * 128u;
        const uint32_t xv = ((uint32_t)lrow & 7u) << 4;
#pragma unroll
        for (int i = 0; i < 4; i++)
            sdst[i] = rb + ((((uint32_t)lhalf) * 64u + (uint32_t)i * 16u) ^ xv);
    }

    // ---- ldmatrix per-lane precompute ----
    const int l8 = lane & 7;
    const int mi = lane >> 3;
    uint32_t aoff[2], ax[2];
#pragma unroll
    for (int s = 0; s < 2; s++) {
        int r = wm * 32 + s * 16 + (mi & 1) * 8 + l8;
        aoff[s] = (uint32_t)r * 128u;
        ax[s]   = ((uint32_t)r & 7u) << 4;
    }
    const uint32_t akb = (uint32_t)(mi >> 1) * 16u;
    uint32_t boff[4], bx[4];
#pragma unroll
    for (int j = 0; j < 4; j++) {
        int r = wn * 64 + j * 16 + (mi >> 1) * 8 + l8;
        boff[j] = (uint32_t)r * 128u;
        bx[j]   = ((uint32_t)r & 7u) << 4;
    }
    const uint32_t bkb = (uint32_t)(mi & 1) * 16u;

    float acc[2][8][4];
#pragma unroll
    for (int s = 0; s < 2; s++)
#pragma unroll
        for (int j = 0; j < 8; j++)
#pragma unroll
            for (int q = 0; q < 4; q++) acc[s][j][q] = 0.f;

    // ---- stage issue: chunk c covers K columns [c*64, c*64+64) ----
    auto issue = [&](int c) {
        const int col = c * 64 + lhalf * 32;
        const uint32_t Ab = sbase + (uint32_t)(c % STAGES) * STG_BYTES;
        const uint32_t Bb = Ab + 16384u;
        const __half* pa = gA + col;
        const __half* pb = gB + col;
#pragma unroll
        for (int i = 0; i < 4; i++) CP_ASYNC16(Ab + sdst[i], pa + i * 8);
#pragma unroll
        for (int i = 0; i < 4; i++) CP_ASYNC16(Bb + sdst[i], pb + i * 8);
        CP_COMMIT();
    };

    issue(0);
    issue(1);

    for (int c = 0; c < NCHUNK; c++) {
        CP_WAIT1();
        __syncthreads();
        const uint32_t Ab = sbase + (uint32_t)(c % STAGES) * STG_BYTES;
        const uint32_t Bb = Ab + 16384u;
#pragma unroll
        for (int kk = 0; kk < 4; kk++) {
            const uint32_t kb = (uint32_t)kk * 32u;
            uint32_t a[2][4];
#pragma unroll
            for (int s = 0; s < 2; s++) {
                uint32_t ad = Ab + aoff[s] + ((kb + akb) ^ ax[s]);
                LDSM_X4(a[s][0], a[s][1], a[s][2], a[s][3], ad);
            }
#pragma unroll
            for (int j = 0; j < 4; j++) {
                uint32_t b[4];
                uint32_t bd = Bb + boff[j] + ((kb + bkb) ^ bx[j]);
                LDSM_X4(b[0], b[1], b[2], b[3], bd);
                MMA_F16(acc[0][2 * j],     a[0], b[0], b[1]);
                MMA_F16(acc[0][2 * j + 1], a[0], b[2], b[3]);
                MMA_F16(acc[1][2 * j],     a[1], b[0], b[1]);
                MMA_F16(acc[1][2 * j + 1], a[1], b[2], b[3]);
            }
        }
        if (c + 2 < NCHUNK) issue(c + 2);
    }

    // ---- epilogue ----
    const int mrow = lane >> 2;
    const int mcol = (lane & 3) * 2;
#pragma unroll
    for (int s = 0; s < 2; s++) {
        const int r1 = row0 + wm * 32 + s * 16 + mrow;
        const int r2 = r1 + 8;
#pragma unroll
        for (int j = 0; j < 8; j++) {
            const int col = col0 + wn * 64 + j * 8 + mcol;
            const float b0v = bias[col], b1v = bias[col + 1];
            float x0 = acc[s][j][0] + b0v, x1 = acc[s][j][1] + b1v;
            float y0 = acc[s][j][2] + b0v, y1 = acc[s][j][3] + b1v;
            if (ACT) { x0 = tanhf(x0); x1 = tanhf(x1); y0 = tanhf(y0); y1 = tanhf(y1); }
            if (r1 < M) {
                if (HOUT) *(uint32_t*)(Ch + (size_t)r1 * N + col) = pack2(x0, x1);
                else      *(float2*)(C + (size_t)r1 * N + col) = make_float2(x0, x1);
                if (SPLIT) *(uint32_t*)(Cs + (size_t)r1 * DIM + col) = pack2(x0, x1);
            }
            if (r2 < M) {
                if (HOUT) *(uint32_t*)(Ch + (size_t)r2 * N + col) = pack2(y0, y1);
                else      *(float2*)(C + (size_t)r2 * N + col) = make_float2(y0, y1);
                if (SPLIT) *(uint32_t*)(Cs + (size_t)r2 * DIM + col) = pack2(y0, y1);
            }
        }
    }
}

// ================= fused preprocessing: all fp32->fp16 conversions in ONE launch ======
__global__ void k_prep(const float* __restrict__ smask, const float* __restrict__ relE,
                       const float* __restrict__ W_sub, const float* __restrict__ W_obj,
                       const float* __restrict__ W_ih,  const float* __restrict__ W_hh,
                       int S, int R)
{
    const int i = blockIdx.x * blockDim.x + threadIdx.x;
    const int task = blockIdx.y;
    const float* src; __half* dst; int tot;
    switch (task) {
    case 0:  src = smask; dst = g_smasks; tot = S * 192;    break;
    case 1:  src = relE;  dst = g_rels;   tot = R * 192;    break;
    case 2:  src = W_sub; dst = g_Wsubs;  tot = DIM * 192;  break;
    case 3:  src = W_obj; dst = g_Wobjs;  tot = DIM * 192;  break;
    case 4:  src = W_ih;  dst = g_Wihs;   tot = DIM3 * 192; break;
    default: src = W_hh;  dst = g_Whhs;   tot = DIM3 * 192; break;
    }
    if (i >= tot) return;
    float4 v = *(const float4*)(src + (size_t)i * 4);
    *(uint2*)(dst + (size_t)i * 4) = pack4(v);
}

__global__ void k_gi_enc(const float* __restrict__ enc, const float* __restrict__ W_ih,
                         const float* __restrict__ b_ih)
{
    int j = blockIdx.x * 8 + (threadIdx.x >> 5);
    int lane = threadIdx.x & 31;
    if (j >= DIM3) return;
    const float* w = W_ih + (size_t)j * DIM;
    float s = 0.f;
#pragma unroll
    for (int k = lane * 4; k < DIM; k += 128) {
        float4 wv = *(const float4*)(w + k);
        float4 ev = *(const float4*)(enc + k);
        s += wv.x * ev.x + wv.y * ev.y + wv.z * ev.z + wv.w * ev.w;
    }
#pragma unroll
    for (int o = 16; o; o >>= 1) s += __shfl_xor_sync(0xffffffffu, s, o);
    if (lane == 0) g_gi_enc[j] = s + b_ih[j];
}

__device__ __forceinline__ float sigm(float x) { return 1.f / (1.f + __expf(-x)); }
__device__ __forceinline__ float gru1(float ir, float iz, float in_,
                                      float hr, float hz, float hn, float h) {
    float r = sigm(ir + hr);
    float z = sigm(iz + hz);
    float n = tanhf(in_ + r * hn);
    return (1.f - z) * n + z * h;
}

// r0 = GRU(enc broadcast, h=sub) -> fp16 (consumed only by gi0 GEMM)
__global__ void k_gru_r0(int S)
{
    int i = blockIdx.x * blockDim.x + threadIdx.x;
    if (i >= S * 192) return;
    int s = i / 192, d = (i - s * 192) * 4;
    const __half* gh = g_ghH + (size_t)s * DIM3;
    float4 ir  = *(const float4*)(g_gi_enc + d);
    float4 iz  = *(const float4*)(g_gi_enc + DIM + d);
    float4 in_ = *(const float4*)(g_gi_enc + 2 * DIM + d);
    float4 hr  = ld4h(gh + d);
    float4 hz  = ld4h(gh + DIM + d);
    float4 hn  = ld4h(gh + 2 * DIM + d);
    float4 hh  = *(const float4*)(g_sub + (size_t)s * DIM + d);
    float4 o;
    o.x = gru1(ir.x, iz.x, in_.x, hr.x, hz.x, hn.x, hh.x);
    o.y = gru1(ir.y, iz.y, in_.y, hr.y, hz.y, hn.y, hh.y);
    o.z = gru1(ir.z, iz.z, in_.z, hr.z, hz.z, hn.z, hh.z);
    o.w = gru1(ir.w, iz.w, in_.w, hr.w, hz.w, hn.w, hh.w);
    *(uint2*)(g_r0s + (size_t)s * DIM + d) = pack4(o);
}

__global__ void k_init(int N)
{
    int i = blockIdx.x * blockDim.x + threadIdx.x;
    if (i < N) { g_best[i] = -1; g_seedpos[i] = -1; }
}
__global__ void k_seed(const int* __restrict__ seeds, int S, int stride)
{
    int s = blockIdx.x * blockDim.x + threadIdx.x;
    if (s >= S) return;
    int node = seeds[s];
    g_seedpos[node] = s;
    atomicMax(&g_best[node], s * stride);
}
__global__ void k_edge(const int* __restrict__ heads, const int* __restrict__ tails,
                       int E, int stride)
{
    int e = blockIdx.x * blockDim.x + threadIdx.x;
    if (e >= E) return;
    int pos = g_seedpos[heads[e]];
    int t = pos * stride + 1 + e;
    atomicMax(&g_best[tails[e]], t);
}

// rj[e] = GRU(gi0[head], ghR[type], h=rel[type]) -> fp16
__global__ void k_rj(const int* __restrict__ heads, const int* __restrict__ types,
                     const float* __restrict__ rel)
{
    int e = blockIdx.x;
    int h = heads[e];
    int t = types[e];
    const __half* gi = g_gi0H + (size_t)h * DIM3;
    const __half* gh = g_ghRH + (size_t)t * DIM3;
    const float*  rl = rel + (size_t)t * DIM;
    int d = threadIdx.x * 4;
    float4 ir  = ld4h(gi + d);
    float4 iz  = ld4h(gi + DIM + d);
    float4 in_ = ld4h(gi + 2 * DIM + d);
    float4 hr  = ld4h(gh + d);
    float4 hz  = ld4h(gh + DIM + d);
    float4 hn  = ld4h(gh + 2 * DIM + d);
    float4 hh  = *(const float4*)(rl + d);
    float4 o;
    o.x = gru1(ir.x, iz.x, in_.x, hr.x, hz.x, hn.x, hh.x);
    o.y = gru1(ir.y, iz.y, in_.y, hr.y, hz.y, hn.y, hh.y);
    o.z = gru1(ir.z, iz.z, in_.z, hr.z, hz.z, hn.z, hh.z);
    o.w = gru1(ir.w, iz.w, in_.w, hr.w, hz.w, hn.w, hh.w);
    *(uint2*)(g_rjs + (size_t)e * DIM + d) = pack4(o);
}

__global__ void k_out(const int* __restrict__ node2node, const int* __restrict__ old_nd,
                      const float* __restrict__ defa, float* __restrict__ out, int stride)
{
    int nrow = blockIdx.x;
    int id = node2node[old_nd[nrow]];
    int b = g_best[id];
    const float* src;
    if (b < 0) {
        src = defa + (size_t)nrow * DIM;
    } else {
        int q = b / stride;
        int rem = b - q * stride;
        src = (rem == 0) ? (g_sub + (size_t)q * DIM)
                         : (g_obj + (size_t)(rem - 1) * DIM);
    }
    int d = threadIdx.x * 4;
    *(float4*)(out + (size_t)nrow * DIM + d) = *(const float4*)(src + d);
}

// ================= host =================
extern "C" void kernel_launch(void* const* d_in, const int* in_sizes, int n_in,
                              void* d_out, int out_size)
{
    const float* enc   = (const float*)d_in[0];
    const float* smask = (const float*)d_in[1];
    const int*   seeds = (const int*)  d_in[2];
    const int*   ehead = (const int*)  d_in[3];
    const int*   etail = (const int*)  d_in[4];
    const int*   etype = (const int*)  d_in[5];
    const int*   n2n   = (const int*)  d_in[6];
    const int*   oldnd = (const int*)  d_in[7];
    const float* relE  = (const float*)d_in[8];
    const float* W_sub = (const float*)d_in[9];
    const float* b_sub = (const float*)d_in[10];
    const float* W_obj = (const float*)d_in[11];
    const float* b_obj = (const float*)d_in[12];
    const float* W_ih  = (const float*)d_in[13];
    const float* W_hh  = (const float*)d_in[14];
    const float* b_ih  = (const float*)d_in[15];
    const float* b_hh  = (const float*)d_in[16];
    const float* defa  = (const float*)d_in[17];
    float* out = (float*)d_out;

    const int S = in_sizes[2];
    const int E = in_sizes[3];
    const int N = in_sizes[6];
    const int R = in_sizes[8] / DIM;
    const int stride = E + 1;

    float *p_sub, *p_obj;
    __half *p_ghH, *p_gi0H, *p_ghRH;
    __half *p_smasks, *p_subs, *p_r0s, *p_rjs, *p_rels,
           *p_Wsubs, *p_Wobjs, *p_Wihs, *p_Whhs;
    cudaGetSymbolAddress((void**)&p_sub,    g_sub);
    cudaGetSymbolAddress((void**)&p_obj,    g_obj);
    cudaGetSymbolAddress((void**)&p_ghH,    g_ghH);
    cudaGetSymbolAddress((void**)&p_gi0H,   g_gi0H);
    cudaGetSymbolAddress((void**)&p_ghRH,   g_ghRH);
    cudaGetSymbolAddress((void**)&p_smasks, g_smasks);
    cudaGetSymbolAddress((void**)&p_subs,   g_subs);
    cudaGetSymbolAddress((void**)&p_r0s,    g_r0s);
    cudaGetSymbolAddress((void**)&p_rjs,    g_rjs);
    cudaGetSymbolAddress((void**)&p_rels,   g_rels);
    cudaGetSymbolAddress((void**)&p_Wsubs,  g_Wsubs);
    cudaGetSymbolAddress((void**)&p_Wobjs,  g_Wobjs);
    cudaGetSymbolAddress((void**)&p_Wihs,   g_Wihs);
    cudaGetSymbolAddress((void**)&p_Whhs,   g_Whhs);

    cudaFuncSetAttribute(gemm_tc<1,1,0>, cudaFuncAttributeMaxDynamicSharedMemorySize, GEMM_SMEM);
    cudaFuncSetAttribute(gemm_tc<0,0,1>, cudaFuncAttributeMaxDynamicSharedMemorySize, GEMM_SMEM);
    cudaFuncSetAttribute(gemm_tc<1,0,0>, cudaFuncAttributeMaxDynamicSharedMemorySize, GEMM_SMEM);

    // independent setup first
    k_init<<<(N + 255) / 256, 256>>>(N);
    {
        dim3 grid((DIM3 * 192 + 255) / 256, 6);
        k_prep<<<grid, 256>>>(smask, relE, W_sub, W_obj, W_ih, W_hh, S, R);
    }
    k_gi_enc<<<(DIM3 + 7) / 8, 256>>>(enc, W_ih, b_ih);
    k_seed<<<(S + 255) / 256, 256>>>(seeds, S, stride);
    k_edge<<<(E + 255) / 256, 256>>>(ehead, etail, E, stride);

    // sub = tanh(mask @ W_sub^T + b_sub)      [S,768] fp32 + fp16 copy
    gemm_tc<1,1,0><<<dim3(DIM / 128, S / 128), 256, GEMM_SMEM>>>(
        p_smasks, p_Wsubs, b_sub, p_sub, p_subs, (__half*)0, S, DIM);
    // gh = sub @ W_hh^T + b_hh                [S,2304] fp16 out
    gemm_tc<0,0,1><<<dim3(DIM3 / 128, S / 128), 256, GEMM_SMEM>>>(
        p_subs, p_Whhs, b_hh, (float*)0, (__half*)0, p_ghH, S, DIM3);
    // r0 = GRU(enc, sub) -> fp16
    k_gru_r0<<<(S * 192 + 255) / 256, 256>>>(S);
    // gi0 = r0 @ W_ih^T + b_ih                [S,2304] fp16 out
    gemm_tc<0,0,1><<<dim3(DIM3 / 128, S / 128), 256, GEMM_SMEM>>>(
        p_r0s, p_Wihs, b_ih, (float*)0, (__half*)0, p_gi0H, S, DIM3);
    // ghR = rel_emb @ W_hh^T + b_hh           [R,2304] fp16 out
    gemm_tc<0,0,1><<<dim3(DIM3 / 128, (R + 127) / 128), 256, GEMM_SMEM>>>(
        p_rels, p_Whhs, b_hh, (float*)0, (__half*)0, p_ghRH, R, DIM3);

    // rj[e] = GRU(gi0[head], rel[type]) -> fp16
    k_rj<<<E, 192>>>(ehead, etype, relE);
    // obj = tanh(rj @ W_obj^T + b_obj)        [E,768] fp32 (dominant GEMM)
    gemm_tc<1,0,0><<<dim3(DIM / 128, E / 128), 256, GEMM_SMEM>>>(
        p_rjs, p_Wobjs, b_obj, p_obj, (__half*)0, (__half*)0, E, DIM);

    k_out<<<N, 192>>>(n2n, oldnd, defa, out, stride);
}

// round 16
// speedup vs baseline: 1.7908x; 1.0053x over previous
#include <cuda_runtime.h>
#include <cuda_fp16.h>
#include <stdint.h>

#define DIM  768
#define DIM3 2304
#define MAX_S 2048
#define MAX_E 32768
#define MAX_N 100000
#define MAX_R 1000

// ---------------- fp32 / int scratch ----------------
__device__ float g_gi_enc[DIM3];
__device__ int   g_best[MAX_N];
__device__ int   g_seedpos[MAX_N];

// ---- fp16 gate pre-activation buffers (GEMM outputs consumed by GRU kernels) ----
__device__ __half g_ghH  [MAX_S * DIM3];
__device__ __half g_gi0H [MAX_S * DIM3];
__device__ __half g_ghRH [MAX_R * DIM3];

// ---- fp16 operand / result buffers: [rows][768] ----
__device__ __half g_smasks[MAX_S * DIM];
__device__ __half g_subs  [MAX_S * DIM];     // tanh(...)  (k_gru_r0 h-input, k_out source)
__device__ __half g_r0s   [MAX_S * DIM];
__device__ __half g_rjs   [(size_t)MAX_E * DIM];
__device__ __half g_objH  [(size_t)MAX_E * DIM];  // tanh(...) (k_out source)
__device__ __half g_rels  [MAX_R * DIM];
// ---- fp16 W-operand scratch: [rows][768] ----
__device__ __half g_Wsubs [DIM  * DIM];
__device__ __half g_Wobjs [DIM  * DIM];
__device__ __half g_Wihs  [DIM3 * DIM];
__device__ __half g_Whhs  [DIM3 * DIM];

// ---------------- helpers ----------------
__device__ __forceinline__ uint32_t smem_u32(const void* p) {
    uint32_t a;
    asm("{ .reg .u64 t; cvta.to.shared.u64 t, %1; cvt.u32.u64 %0, t; }" : "=r"(a) : "l"(p));
    return a;
}

union HQ { __half h[4]; uint2 u; };
__device__ __forceinline__ uint2 pack4(float4 v) {
    HQ H;
    H.h[0] = __float2half_rn(v.x); H.h[1] = __float2half_rn(v.y);
    H.h[2] = __float2half_rn(v.z); H.h[3] = __float2half_rn(v.w);
    return H.u;
}
union HP { __half h[2]; uint32_t u; };
__device__ __forceinline__ uint32_t pack2(float x0, float x1) {
    HP P; P.h[0] = __float2half_rn(x0); P.h[1] = __float2half_rn(x1);
    return P.u;
}
__device__ __forceinline__ float4 ld4h(const __half* p) {
    uint2 u = *(const uint2*)p;
    float2 f0 = __half22float2(*(__half2*)&u.x);
    float2 f1 = __half22float2(*(__half2*)&u.y);
    return make_float4(f0.x, f0.y, f1.x, f1.y);
}

#define LDSM_X4(r0, r1, r2, r3, addr) \
    asm volatile("ldmatrix.sync.aligned.m8n8.x4.shared.b16 {%0,%1,%2,%3}, [%4];" \
        : "=r"(r0), "=r"(r1), "=r"(r2), "=r"(r3) : "r"(addr))

#define MMA_F16(d, a, b0v, b1v) \
    asm volatile("mma.sync.aligned.m16n8k16.row.col.f32.f16.f16.f32 " \
        "{%0,%1,%2,%3}, {%4,%5,%6,%7}, {%8,%9}, {%0,%1,%2,%3};" \
        : "+f"((d)[0]), "+f"((d)[1]), "+f"((d)[2]), "+f"((d)[3]) \
        : "r"((a)[0]), "r"((a)[1]), "r"((a)[2]), "r"((a)[3]), "r"(b0v), "r"(b1v))

#define CP_ASYNC16(dst, src) \
    asm volatile("cp.async.cg.shared.global [%0], [%1], 16;" :: "r"(dst), "l"(src))
#define CP_COMMIT()  asm volatile("cp.async.commit_group;" ::: "memory")
#define CP_WAIT1()   asm volatile("cp.async.wait_group 1;" ::: "memory")

// ================= tensor-core GEMM (mma.sync fp16, K=768, fp16 out) =========
// Ch[M,N] = act(A @ W^T + bias). A,W: fp16 [rows][768]. fp32 accumulate.
// Tile 128x128, BK=64, 256 thr (8 warps, 4m x 2n, warp tile 32x64), 3-stage cp.async, occ 2.
#define STAGES 3
#define STG_BYTES 32768
#define GEMM_SMEM (STAGES * STG_BYTES + 128)
#define NCHUNK 12

template<int ACT>
__global__ __launch_bounds__(256, 2)
void gemm_tc(const __half* __restrict__ A, const __half* __restrict__ W,
             const float* __restrict__ bias, __half* __restrict__ Ch, int M, int N)
{
    extern __shared__ char smraw[];
    const uint32_t sbase = (smem_u32(smraw) + 127u) & ~127u;

    const int tid  = threadIdx.x;
    const int lane = tid & 31;
    const int wid  = tid >> 5;
    const int wm   = wid & 3;          // m offset 32*wm
    const int wn   = wid >> 2;         // n offset 64*wn
    const int row0 = blockIdx.y * 128;
    const int col0 = blockIdx.x * 128;

    // ---- loader precompute: thread covers row tid/2, 64B half (tid&1) ----
    const int lrow  = tid >> 1;
    const int lhalf = tid & 1;
    const int arow  = min(row0 + lrow, M - 1);      // clamp: extra rows never stored
    const __half* gA = A + (size_t)arow * DIM;
    const __half* gB = W + (size_t)(col0 + lrow) * DIM;
    uint32_t sdst[4];
    {
        const uint32_t rb = (uint32_t)lrow * 128u;
        const uint32_t xv = ((uint32_t)lrow & 7u) << 4;
#pragma unroll
        for (int i = 0; i < 4; i++)
            sdst[i] = rb + ((((uint32_t)lhalf) * 64u + (uint32_t)i * 16u) ^ xv);
    }

    // ---- ldmatrix per-lane precompute ----
    const int l8 = lane & 7;
    const int mi = lane >> 3;
    uint32_t aoff[2], ax[2];
#pragma unroll
    for (int s = 0; s < 2; s++) {
        int r = wm * 32 + s * 16 + (mi & 1) * 8 + l8;
        aoff[s] = (uint32_t)r * 128u;
        ax[s]   = ((uint32_t)r & 7u) << 4;
    }
    const uint32_t akb = (uint32_t)(mi >> 1) * 16u;
    uint32_t boff[4], bx[4];
#pragma unroll
    for (int j = 0; j < 4; j++) {
        int r = wn * 64 + j * 16 + (mi >> 1) * 8 + l8;
        boff[j] = (uint32_t)r * 128u;
        bx[j]   = ((uint32_t)r & 7u) << 4;
    }
    const uint32_t bkb = (uint32_t)(mi & 1) * 16u;

    float acc[2][8][4];
#pragma unroll
    for (int s = 0; s < 2; s++)
#pragma unroll
        for (int j = 0; j < 8; j++)
#pragma unroll
            for (int q = 0; q < 4; q++) acc[s][j][q] = 0.f;

    // ---- stage issue: chunk c covers K columns [c*64, c*64+64) ----
    auto issue = [&](int c) {
        const int col = c * 64 + lhalf * 32;
        const uint32_t Ab = sbase + (uint32_t)(c % STAGES) * STG_BYTES;
        const uint32_t Bb = Ab + 16384u;
        const __half* pa = gA + col;
        const __half* pb = gB + col;
#pragma unroll
        for (int i = 0; i < 4; i++) CP_ASYNC16(Ab + sdst[i], pa + i * 8);
#pragma unroll
        for (int i = 0; i < 4; i++) CP_ASYNC16(Bb + sdst[i], pb + i * 8);
        CP_COMMIT();
    };

    issue(0);
    issue(1);

    for (int c = 0; c < NCHUNK; c++) {
        CP_WAIT1();
        __syncthreads();
        const uint32_t Ab = sbase + (uint32_t)(c % STAGES) * STG_BYTES;
        const uint32_t Bb = Ab + 16384u;
#pragma unroll
        for (int kk = 0; kk < 4; kk++) {
            const uint32_t kb = (uint32_t)kk * 32u;
            uint32_t a[2][4];
#pragma unroll
            for (int s = 0; s < 2; s++) {
                uint32_t ad = Ab + aoff[s] + ((kb + akb) ^ ax[s]);
                LDSM_X4(a[s][0], a[s][1], a[s][2], a[s][3], ad);
            }
#pragma unroll
            for (int j = 0; j < 4; j++) {
                uint32_t b[4];
                uint32_t bd = Bb + boff[j] + ((kb + bkb) ^ bx[j]);
                LDSM_X4(b[0], b[1], b[2], b[3], bd);
                MMA_F16(acc[0][2 * j],     a[0], b[0], b[1]);
                MMA_F16(acc[0][2 * j + 1], a[0], b[2], b[3]);
                MMA_F16(acc[1][2 * j],     a[1], b[0], b[1]);
                MMA_F16(acc[1][2 * j + 1], a[1], b[2], b[3]);
            }
        }
        if (c + 2 < NCHUNK) issue(c + 2);
    }

    // ---- epilogue (fp16 out) ----
    const int mrow = lane >> 2;
    const int mcol = (lane & 3) * 2;
#pragma unroll
    for (int s = 0; s < 2; s++) {
        const int r1 = row0 + wm * 32 + s * 16 + mrow;
        const int r2 = r1 + 8;
#pragma unroll
        for (int j = 0; j < 8; j++) {
            const int col = col0 + wn * 64 + j * 8 + mcol;
            const float b0v = bias[col], b1v = bias[col + 1];
            float x0 = acc[s][j][0] + b0v, x1 = acc[s][j][1] + b1v;
            float y0 = acc[s][j][2] + b0v, y1 = acc[s][j][3] + b1v;
            if (ACT) { x0 = tanhf(x0); x1 = tanhf(x1); y0 = tanhf(y0); y1 = tanhf(y1); }
            if (r1 < M) *(uint32_t*)(Ch + (size_t)r1 * N + col) = pack2(x0, x1);
            if (r2 < M) *(uint32_t*)(Ch + (size_t)r2 * N + col) = pack2(y0, y1);
        }
    }
}

// ================= fused preprocessing: all fp32->fp16 conversions in ONE launch ======
__global__ void k_prep(const float* __restrict__ smask, const float* __restrict__ relE,
                       const float* __restrict__ W_sub, const float* __restrict__ W_obj,
                       const float* __restrict__ W_ih,  const float* __restrict__ W_hh,
                       int S, int R)
{
    const int i = blockIdx.x * blockDim.x + threadIdx.x;
    const int task = blockIdx.y;
    const float* src; __half* dst; int tot;
    switch (task) {
    case 0:  src = smask; dst = g_smasks; tot = S * 192;    break;
    case 1:  src = relE;  dst = g_rels;   tot = R * 192;    break;
    case 2:  src = W_sub; dst = g_Wsubs;  tot = DIM * 192;  break;
    case 3:  src = W_obj; dst = g_Wobjs;  tot = DIM * 192;  break;
    case 4:  src = W_ih;  dst = g_Wihs;   tot = DIM3 * 192; break;
    default: src = W_hh;  dst = g_Whhs;   tot = DIM3 * 192; break;
    }
    if (i >= tot) return;
    float4 v = *(const float4*)(src + (size_t)i * 4);
    *(uint2*)(dst + (size_t)i * 4) = pack4(v);
}

__global__ void k_gi_enc(const float* __restrict__ enc, const float* __restrict__ W_ih,
                         const float* __restrict__ b_ih)
{
    int j = blockIdx.x * 8 + (threadIdx.x >> 5);
    int lane = threadIdx.x & 31;
    if (j >= DIM3) return;
    const float* w = W_ih + (size_t)j * DIM;
    float s = 0.f;
#pragma unroll
    for (int k = lane * 4; k < DIM; k += 128) {
        float4 wv = *(const float4*)(w + k);
        float4 ev = *(const float4*)(enc + k);
        s += wv.x * ev.x + wv.y * ev.y + wv.z * ev.z + wv.w * ev.w;
    }
#pragma unroll
    for (int o = 16; o; o >>= 1) s += __shfl_xor_sync(0xffffffffu, s, o);
    if (lane == 0) g_gi_enc[j] = s + b_ih[j];
}

__device__ __forceinline__ float sigm(float x) { return 1.f / (1.f + __expf(-x)); }
__device__ __forceinline__ float gru1(float ir, float iz, float in_,
                                      float hr, float hz, float hn, float h) {
    float r = sigm(ir + hr);
    float z = sigm(iz + hz);
    float n = tanhf(in_ + r * hn);
    return (1.f - z) * n + z * h;
}

// r0 = GRU(enc broadcast, h=sub fp16) -> fp16 (consumed only by gi0 GEMM)
__global__ void k_gru_r0(int S)
{
    int i = blockIdx.x * blockDim.x + threadIdx.x;
    if (i >= S * 192) return;
    int s = i / 192, d = (i - s * 192) * 4;
    const __half* gh = g_ghH + (size_t)s * DIM3;
    float4 ir  = *(const float4*)(g_gi_enc + d);
    float4 iz  = *(const float4*)(g_gi_enc + DIM + d);
    float4 in_ = *(const float4*)(g_gi_enc + 2 * DIM + d);
    float4 hr  = ld4h(gh + d);
    float4 hz  = ld4h(gh + DIM + d);
    float4 hn  = ld4h(gh + 2 * DIM + d);
    float4 hh  = ld4h(g_subs + (size_t)s * DIM + d);
    float4 o;
    o.x = gru1(ir.x, iz.x, in_.x, hr.x, hz.x, hn.x, hh.x);
    o.y = gru1(ir.y, iz.y, in_.y, hr.y, hz.y, hn.y, hh.y);
    o.z = gru1(ir.z, iz.z, in_.z, hr.z, hz.z, hn.z, hh.z);
    o.w = gru1(ir.w, iz.w, in_.w, hr.w, hz.w, hn.w, hh.w);
    *(uint2*)(g_r0s + (size_t)s * DIM + d) = pack4(o);
}

__global__ void k_init(int N)
{
    int i = blockIdx.x * blockDim.x + threadIdx.x;
    if (i < N) { g_best[i] = -1; g_seedpos[i] = -1; }
}
__global__ void k_seed(const int* __restrict__ seeds, int S, int stride)
{
    int s = blockIdx.x * blockDim.x + threadIdx.x;
    if (s >= S) return;
    int node = seeds[s];
    g_seedpos[node] = s;
    atomicMax(&g_best[node], s * stride);
}
__global__ void k_edge(const int* __restrict__ heads, const int* __restrict__ tails,
                       int E, int stride)
{
    int e = blockIdx.x * blockDim.x + threadIdx.x;
    if (e >= E) return;
    int pos = g_seedpos[heads[e]];
    int t = pos * stride + 1 + e;
    atomicMax(&g_best[tails[e]], t);
}

// rj[e] = GRU(gi0[head], ghR[type], h=rel[type]) -> fp16
__global__ void k_rj(const int* __restrict__ heads, const int* __restrict__ types)
{
    int e = blockIdx.x;
    int h = heads[e];
    int t = types[e];
    const __half* gi = g_gi0H + (size_t)h * DIM3;
    const __half* gh = g_ghRH + (size_t)t * DIM3;
    const __half* rl = g_rels + (size_t)t * DIM;
    int d = threadIdx.x * 4;
    float4 ir  = ld4h(gi + d);
    float4 iz  = ld4h(gi + DIM + d);
    float4 in_ = ld4h(gi + 2 * DIM + d);
    float4 hr  = ld4h(gh + d);
    float4 hz  = ld4h(gh + DIM + d);
    float4 hn  = ld4h(gh + 2 * DIM + d);
    float4 hh  = ld4h(rl + d);
    float4 o;
    o.x = gru1(ir.x, iz.x, in_.x, hr.x, hz.x, hn.x, hh.x);
    o.y = gru1(ir.y, iz.y, in_.y, hr.y, hz.y, hn.y, hh.y);
    o.z = gru1(ir.z, iz.z, in_.z, hr.z, hz.z, hn.z, hh.z);
    o.w = gru1(ir.w, iz.w, in_.w, hr.w, hz.w, hn.w, hh.w);
    *(uint2*)(g_rjs + (size_t)e * DIM + d) = pack4(o);
}

// output: decode winner timestamp, gather (fp16 sources -> fp32 out)
__global__ void k_out(const int* __restrict__ node2node, const int* __restrict__ old_nd,
                      const float* __restrict__ defa, float* __restrict__ out, int stride)
{
    int nrow = blockIdx.x;
    int id = node2node[old_nd[nrow]];
    int b = g_best[id];
    int d = threadIdx.x * 4;
    float4 v;
    if (b < 0) {
        v = *(const float4*)(defa + (size_t)nrow * DIM + d);
    } else {
        int q = b / stride;
        int rem = b - q * stride;
        const __half* src = (rem == 0) ? (g_subs + (size_t)q * DIM)
                                       : (g_objH + (size_t)(rem - 1) * DIM);
        v = ld4h(src + d);
    }
    *(float4*)(out + (size_t)nrow * DIM + d) = v;
}

// ================= host =================
extern "C" void kernel_launch(void* const* d_in, const int* in_sizes, int n_in,
                              void* d_out, int out_size)
{
    const float* enc   = (const float*)d_in[0];
    const float* smask = (const float*)d_in[1];
    const int*   seeds = (const int*)  d_in[2];
    const int*   ehead = (const int*)  d_in[3];
    const int*   etail = (const int*)  d_in[4];
    const int*   etype = (const int*)  d_in[5];
    const int*   n2n   = (const int*)  d_in[6];
    const int*   oldnd = (const int*)  d_in[7];
    const float* relE  = (const float*)d_in[8];
    const float* W_sub = (const float*)d_in[9];
    const float* b_sub = (const float*)d_in[10];
    const float* W_obj = (const float*)d_in[11];
    const float* b_obj = (const float*)d_in[12];
    const float* W_ih  = (const float*)d_in[13];
    const float* W_hh  = (const float*)d_in[14];
    const float* b_ih  = (const float*)d_in[15];
    const float* b_hh  = (const float*)d_in[16];
    const float* defa  = (const float*)d_in[17];
    float* out = (float*)d_out;

    const int S = in_sizes[2];
    const int E = in_sizes[3];
    const int N = in_sizes[6];
    const int R = in_sizes[8] / DIM;
    const int stride = E + 1;

    __half *p_ghH, *p_gi0H, *p_ghRH, *p_objH;
    __half *p_smasks, *p_subs, *p_r0s, *p_rjs, *p_rels,
           *p_Wsubs, *p_Wobjs, *p_Wihs, *p_Whhs;
    cudaGetSymbolAddress((void**)&p_ghH,    g_ghH);
    cudaGetSymbolAddress((void**)&p_gi0H,   g_gi0H);
    cudaGetSymbolAddress((void**)&p_ghRH,   g_ghRH);
    cudaGetSymbolAddress((void**)&p_objH,   g_objH);
    cudaGetSymbolAddress((void**)&p_smasks, g_smasks);
    cudaGetSymbolAddress((void**)&p_subs,   g_subs);
    cudaGetSymbolAddress((void**)&p_r0s,    g_r0s);
    cudaGetSymbolAddress((void**)&p_rjs,    g_rjs);
    cudaGetSymbolAddress((void**)&p_rels,   g_rels);
    cudaGetSymbolAddress((void**)&p_Wsubs,  g_Wsubs);
    cudaGetSymbolAddress((void**)&p_Wobjs,  g_Wobjs);
    cudaGetSymbolAddress((void**)&p_Wihs,   g_Wihs);
    cudaGetSymbolAddress((void**)&p_Whhs,   g_Whhs);

    cudaFuncSetAttribute(gemm_tc<1>, cudaFuncAttributeMaxDynamicSharedMemorySize, GEMM_SMEM);
    cudaFuncSetAttribute(gemm_tc<0>, cudaFuncAttributeMaxDynamicSharedMemorySize, GEMM_SMEM);

    // (1) init + prep, then the GEMM chain immediately (ncu slot #4 -> gh GEMM)
    k_init<<<(N + 255) / 256, 256>>>(N);
    {
        dim3 grid((DIM3 * 192 + 255) / 256, 6);
        k_prep<<<grid, 256>>>(smask, relE, W_sub, W_obj, W_ih, W_hh, S, R);
    }

    // sub = tanh(mask @ W_sub^T + b_sub)      [S,768] fp16
    gemm_tc<1><<<dim3(DIM / 128, S / 128), 256, GEMM_SMEM>>>(
        p_smasks, p_Wsubs, b_sub, p_subs, S, DIM);
    // gh = sub @ W_hh^T + b_hh                [S,2304] fp16
    gemm_tc<0><<<dim3(DIM3 / 128, S / 128), 256, GEMM_SMEM>>>(
        p_subs, p_Whhs, b_hh, p_ghH, S, DIM3);
    // ghR = rel_emb @ W_hh^T + b_hh           [R,2304] fp16
    gemm_tc<0><<<dim3(DIM3 / 128, (R + 127) / 128), 256, GEMM_SMEM>>>(
        p_rels, p_Whhs, b_hh, p_ghRH, R, DIM3);

    k_gi_enc<<<(DIM3 + 7) / 8, 256>>>(enc, W_ih, b_ih);
    // r0 = GRU(enc, sub) -> fp16
    k_gru_r0<<<(S * 192 + 255) / 256, 256>>>(S);
    // gi0 = r0 @ W_ih^T + b_ih                [S,2304] fp16
    gemm_tc<0><<<dim3(DIM3 / 128, S / 128), 256, GEMM_SMEM>>>(
        p_r0s, p_Wihs, b_ih, p_gi0H, S, DIM3);

    k_seed<<<(S + 255) / 256, 256>>>(seeds, S, stride);
    k_edge<<<(E + 255) / 256, 256>>>(ehead, etail, E, stride);

    // rj[e] = GRU(gi0[head], rel[type]) -> fp16
    k_rj<<<E, 192>>>(ehead, etype);
    // obj = tanh(rj @ W_obj^T + b_obj)        [E,768] fp16 (dominant GEMM)
    gemm_tc<1><<<dim3(DIM / 128, E / 128), 256, GEMM_SMEM>>>(
        p_rjs, p_Wobjs, b_obj, p_objH, E, DIM);

    k_out<<<N, 192>>>(n2n, oldnd, defa, out, stride);
}